// round 14
// baseline (speedup 1.0000x reference)
#include <cuda_runtime.h>
#include <cuda_fp16.h>

// ---------------- problem constants ----------------
#define NN 50000      // nodes
#define NE 800000     // edges
#define IC 128        // input channels
#define F1 128        // layer1 out = heads*hid = 4*32
#define H  4          // layer1 heads
#define F2 64         // layer2 out channels
#define SCAN_B 1024
#define NBLK ((NN + SCAN_B - 1) / SCAN_B)   // 49

// ---------------- device scratch ----------------
__device__ __half g_h1h[NN * F1];   // layer1 node features, fp16 (gather payload)
__device__ float g_as1[NN * H];
__device__ float g_ad1[NN * H];
__device__ __half g_out1h[NN * F1]; // layer1 output (norm+bias+elu), fp16
__device__ __half g_h2h[NN * F2];   // layer2 node features, fp16
__device__ float g_as2[NN];
__device__ float g_ad2[NN];
__device__ int   g_cnt[NN];         // degree histogram / scatter counters
__device__ int   g_rowptr[NN + 1];
__device__ int   g_csrc[NE];        // src ids sorted by dst (CSR)
__device__ int   g_bsum[NBLK];
__device__ int   g_boff[NBLK];

// ---------------- helpers ----------------
__device__ __forceinline__ float lrexp(float t) {
    t = t > 0.f ? t : 0.2f * t;      // LeakyReLU(0.2)
    return __expf(t);
}

__device__ __forceinline__ int detect_is64(const int* __restrict__ raw) {
    int nz = 0;
#pragma unroll
    for (int k = 0; k < 64; k++) nz |= raw[2 * (k * 631) + 1];
    return (nz == 0) ? 1 : 0;
}

// ---------------- CSR build ----------------
__global__ void zero_cnt() {
    int i = blockIdx.x * blockDim.x + threadIdx.x;
    if (i < NN) g_cnt[i] = 0;
}

__global__ void hist_edges(const int* __restrict__ raw) {
    __shared__ int s_is64;
    if (threadIdx.x == 0) s_is64 = detect_is64(raw);
    __syncthreads();
    int i = blockIdx.x * blockDim.x + threadIdx.x;
    if (i >= NE) return;
    int d = s_is64 ? reinterpret_cast<const int2*>(raw)[NE + i].x : raw[NE + i];
    atomicAdd(&g_cnt[d], 1);
}

__global__ void scanA() {
    __shared__ int s[32];
    int idx = blockIdx.x * SCAN_B + threadIdx.x;
    int v = (idx < NN) ? g_cnt[idx] : 0;
#pragma unroll
    for (int o = 16; o > 0; o >>= 1) v += __shfl_down_sync(0xffffffffu, v, o);
    if ((threadIdx.x & 31) == 0) s[threadIdx.x >> 5] = v;
    __syncthreads();
    if (threadIdx.x < 32) {
        int u = s[threadIdx.x];
#pragma unroll
        for (int o = 16; o > 0; o >>= 1) u += __shfl_down_sync(0xffffffffu, u, o);
        if (threadIdx.x == 0) g_bsum[blockIdx.x] = u;
    }
}

__global__ void scanB() {
    __shared__ int s[64];
    int t = threadIdx.x;
    int v = (t < NBLK) ? g_bsum[t] : 0;
    s[t] = v;
    __syncthreads();
#pragma unroll
    for (int off = 1; off < 64; off <<= 1) {
        int u = (t >= off) ? s[t - off] : 0;
        __syncthreads();
        s[t] += u;
        __syncthreads();
    }
    if (t < NBLK) g_boff[t] = s[t] - v;   // exclusive
}

__global__ void scanC() {
    __shared__ int s[SCAN_B];
    int t = threadIdx.x;
    int idx = blockIdx.x * SCAN_B + t;
    int v = (idx < NN) ? g_cnt[idx] : 0;
    s[t] = v;
    __syncthreads();
    for (int off = 1; off < SCAN_B; off <<= 1) {
        int u = (t >= off) ? s[t - off] : 0;
        __syncthreads();
        s[t] += u;
        __syncthreads();
    }
    int excl = s[t] - v + g_boff[blockIdx.x];
    if (idx < NN) {
        g_rowptr[idx] = excl;
        g_cnt[idx] = 0;
    }
    if (idx == NN - 1) g_rowptr[NN] = excl + v;
}

__global__ void scatter_edges(const int* __restrict__ raw) {
    __shared__ int s_is64;
    if (threadIdx.x == 0) s_is64 = detect_is64(raw);
    __syncthreads();
    int i = blockIdx.x * blockDim.x + threadIdx.x;
    if (i >= NE) return;
    int s, d;
    if (s_is64) {
        s = reinterpret_cast<const int2*>(raw)[i].x;
        d = reinterpret_cast<const int2*>(raw)[NE + i].x;
    } else {
        s = raw[i];
        d = raw[NE + i];
    }
    int pos = g_rowptr[d] + atomicAdd(&g_cnt[d], 1);
    g_csrc[pos] = s;
}

// ---------------- SGEMM + fused attention-coefficient epilogue ----------------
// LAYER=1: A = x (fp32), C = g_h1h fp16; epilogue -> g_as1/g_ad1
// LAYER=2: A = g_out1h (fp16, converted on load), C = g_h2h; epilogue -> g_as2/g_ad2
template <int BM, int BN, int BK, int TM, int TN, int LAYER>
__global__ void __launch_bounds__((BM / TM) * (BN / TN), 2)
sgemm(const float* __restrict__ Ain, const float* __restrict__ B,
      const float* __restrict__ attS, const float* __restrict__ attD, int M) {
    constexpr int K = 128;
    constexpr int NT = (BM / TM) * (BN / TN);
    constexpr int A_IT = BM * BK / (4 * NT);
    constexpr int B_IT = BK * BN / (4 * NT);
    __half* C = (LAYER == 1) ? g_h1h : g_h2h;

    __shared__ __align__(16) float As[2][BK][BM];   // transposed: As[k][m]
    __shared__ __align__(16) float Bs[2][BK][BN];

    const int tid  = threadIdx.x;
    const int trow = tid / (BN / TN);
    const int tcol = tid % (BN / TN);
    const int rowBase = blockIdx.x * BM;

    float4 aReg[A_IT], bReg[B_IT];

    auto gload = [&](int k0) {
#pragma unroll
        for (int it = 0; it < A_IT; it++) {
            int i = (tid + it * NT) * 4;
            int r = i / BK, c = i % BK;
            int gr = rowBase + r;
            float4 v = make_float4(0.f, 0.f, 0.f, 0.f);
            if (gr < M) {
                if (LAYER == 1) {
                    v = *reinterpret_cast<const float4*>(&Ain[(long)gr * K + k0 + c]);
                } else {
                    uint2 hv = *reinterpret_cast<const uint2*>(&g_out1h[(long)gr * K + k0 + c]);
                    float2 lo = __half22float2(*reinterpret_cast<__half2*>(&hv.x));
                    float2 hi = __half22float2(*reinterpret_cast<__half2*>(&hv.y));
                    v = make_float4(lo.x, lo.y, hi.x, hi.y);
                }
            }
            aReg[it] = v;
        }
#pragma unroll
        for (int it = 0; it < B_IT; it++) {
            int i = (tid + it * NT) * 4;
            int r = i / BN, c = i % BN;
            bReg[it] = *reinterpret_cast<const float4*>(&B[(long)(k0 + r) * BN + c]);
        }
    };

    auto sstore = [&](int buf) {
#pragma unroll
        for (int it = 0; it < A_IT; it++) {
            int i = (tid + it * NT) * 4;
            int r = i / BK, c = i % BK;
            As[buf][c + 0][r] = aReg[it].x;
            As[buf][c + 1][r] = aReg[it].y;
            As[buf][c + 2][r] = aReg[it].z;
            As[buf][c + 3][r] = aReg[it].w;
        }
#pragma unroll
        for (int it = 0; it < B_IT; it++) {
            int i = (tid + it * NT) * 4;
            int r = i / BN, c = i % BN;
            *reinterpret_cast<float4*>(&Bs[buf][r][c]) = bReg[it];
        }
    };

    float acc[TM][TN];
#pragma unroll
    for (int m = 0; m < TM; m++)
#pragma unroll
        for (int n = 0; n < TN; n++) acc[m][n] = 0.f;

    auto compute = [&](int buf) {
#pragma unroll
        for (int k = 0; k < BK; k++) {
            float ra[TM], rb[TN];
#pragma unroll
            for (int m = 0; m < TM; m += 4)
                *reinterpret_cast<float4*>(&ra[m]) =
                    *reinterpret_cast<const float4*>(&As[buf][k][trow * TM + m]);
#pragma unroll
            for (int n = 0; n < TN; n += 4)
                *reinterpret_cast<float4*>(&rb[n]) =
                    *reinterpret_cast<const float4*>(&Bs[buf][k][tcol * TN + n]);
#pragma unroll
            for (int m = 0; m < TM; m++)
#pragma unroll
                for (int n = 0; n < TN; n++)
                    acc[m][n] = fmaf(ra[m], rb[n], acc[m][n]);
        }
    };

    gload(0);
    sstore(0);
    __syncthreads();
    int buf = 0;
    for (int k0 = BK; k0 < K; k0 += BK) {
        gload(k0);
        compute(buf);
        sstore(buf ^ 1);
        __syncthreads();
        buf ^= 1;
    }
    compute(buf);

    // ---- write C tile in fp16 ----
#pragma unroll
    for (int m = 0; m < TM; m++) {
        int gr = rowBase + trow * TM + m;
        if (gr < M) {
            unsigned int packed[TN / 2];
#pragma unroll
            for (int n = 0; n < TN; n += 2) {
                __half2 h = __float22half2_rn(make_float2(acc[m][n], acc[m][n + 1]));
                packed[n / 2] = *reinterpret_cast<unsigned int*>(&h);
            }
            __half* dst = &C[(long)gr * BN + tcol * TN];
            if (TN == 8) {
                *reinterpret_cast<uint4*>(dst) =
                    make_uint4(packed[0], packed[1], packed[2], packed[3]);
            } else {
                *reinterpret_cast<uint2*>(dst) = make_uint2(packed[0], packed[1]);
            }
        }
    }

    // ---- fused attention epilogue (fp32 acc) ----
    float asr[TN], adr[TN];
#pragma unroll
    for (int n = 0; n < TN; n++) {
        asr[n] = attS[tcol * TN + n];
        adr[n] = attD[tcol * TN + n];
    }
    float pa[TM], pd[TM];
#pragma unroll
    for (int m = 0; m < TM; m++) {
        float a = 0.f, b = 0.f;
#pragma unroll
        for (int n = 0; n < TN; n++) {
            a = fmaf(acc[m][n], asr[n], a);
            b = fmaf(acc[m][n], adr[n], b);
        }
        if (LAYER == 1) {
            a += __shfl_down_sync(0xffffffffu, a, 2);
            a += __shfl_down_sync(0xffffffffu, a, 1);
            b += __shfl_down_sync(0xffffffffu, b, 2);
            b += __shfl_down_sync(0xffffffffu, b, 1);
        } else {
            a += __shfl_down_sync(0xffffffffu, a, 8);
            a += __shfl_down_sync(0xffffffffu, a, 4);
            a += __shfl_down_sync(0xffffffffu, a, 2);
            a += __shfl_down_sync(0xffffffffu, a, 1);
            b += __shfl_down_sync(0xffffffffu, b, 8);
            b += __shfl_down_sync(0xffffffffu, b, 4);
            b += __shfl_down_sync(0xffffffffu, b, 2);
            b += __shfl_down_sync(0xffffffffu, b, 1);
        }
        pa[m] = a;
        pd[m] = b;
    }

    float* sA = &Bs[0][0][0];
    float* sD = sA + BM * H;
    __syncthreads();

    if (LAYER == 1) {
        if ((tcol & 3) == 0) {
            int head = tcol >> 2;
#pragma unroll
            for (int m = 0; m < TM; m++) {
                sA[(trow * TM + m) * H + head] = pa[m];
                sD[(trow * TM + m) * H + head] = pd[m];
            }
        }
        __syncthreads();
        if (tid < BM) {
            int gr = rowBase + tid;
            if (gr < M) {
                *reinterpret_cast<float4*>(&g_as1[gr * H]) =
                    *reinterpret_cast<const float4*>(&sA[tid * H]);
                *reinterpret_cast<float4*>(&g_ad1[gr * H]) =
                    *reinterpret_cast<const float4*>(&sD[tid * H]);
            }
        }
    } else {
        if (tcol == 0) {
#pragma unroll
            for (int m = 0; m < TM; m++) {
                sA[trow * TM + m] = pa[m];
                sD[trow * TM + m] = pd[m];
            }
        }
        __syncthreads();
        if (tid < BM) {
            int gr = rowBase + tid;
            if (gr < M) {
                g_as2[gr] = sA[tid];
                g_ad2[gr] = sD[tid];
            }
        }
    }
}

// ---------------- layer-1 aggregation: one warp per dst node (R7 structure) ----------------
__global__ void __launch_bounds__(256, 8) agg1(const float* __restrict__ b1) {
    __shared__ __align__(16) float sp[8][32][4];   // staged p per head
    __shared__ int ssrc[8][32];
    const int wid  = threadIdx.x >> 5;
    const int lane = threadIdx.x & 31;
    const int n    = (blockIdx.x * blockDim.x + threadIdx.x) >> 5;
    if (n >= NN) return;
    const int beg = g_rowptr[n], end = g_rowptr[n + 1];
    const int head = lane >> 3;
    const float4 ad = *reinterpret_cast<const float4*>(&g_ad1[n * H]);
    const uint2* hp = reinterpret_cast<const uint2*>(g_h1h);   // 4 halves per uint2

    float4 sumv = make_float4(0.f, 0.f, 0.f, 0.f);
    float4 acc0 = make_float4(0.f, 0.f, 0.f, 0.f);
    float4 acc1 = make_float4(0.f, 0.f, 0.f, 0.f);

    for (int e0 = beg; e0 < end; e0 += 32) {
        const int m = min(32, end - e0);
        float4 p4 = make_float4(0.f, 0.f, 0.f, 0.f);
        int s = 0;
        if (lane < m) {
            s = g_csrc[e0 + lane];
            float4 as = *reinterpret_cast<const float4*>(&g_as1[s * H]);
            p4.x = lrexp(as.x + ad.x);
            p4.y = lrexp(as.y + ad.y);
            p4.z = lrexp(as.z + ad.z);
            p4.w = lrexp(as.w + ad.w);
        }
        sumv.x += p4.x; sumv.y += p4.y; sumv.z += p4.z; sumv.w += p4.w;
        *reinterpret_cast<float4*>(&sp[wid][lane][0]) = p4;
        ssrc[wid][lane] = s;
        __syncwarp();
        int j = 0;
        for (; j + 2 <= m; j += 2) {
            int s0 = ssrc[wid][j + 0];
            int s1 = ssrc[wid][j + 1];
            float a0 = sp[wid][j + 0][head];
            float a1 = sp[wid][j + 1][head];
            uint2 r0 = hp[s0 * (F1 / 4) + lane];
            uint2 r1 = hp[s1 * (F1 / 4) + lane];
            float2 f00 = __half22float2(*reinterpret_cast<__half2*>(&r0.x));
            float2 f01 = __half22float2(*reinterpret_cast<__half2*>(&r0.y));
            float2 f10 = __half22float2(*reinterpret_cast<__half2*>(&r1.x));
            float2 f11 = __half22float2(*reinterpret_cast<__half2*>(&r1.y));
            acc0.x = fmaf(a0, f00.x, acc0.x); acc0.y = fmaf(a0, f00.y, acc0.y);
            acc0.z = fmaf(a0, f01.x, acc0.z); acc0.w = fmaf(a0, f01.y, acc0.w);
            acc1.x = fmaf(a1, f10.x, acc1.x); acc1.y = fmaf(a1, f10.y, acc1.y);
            acc1.z = fmaf(a1, f11.x, acc1.z); acc1.w = fmaf(a1, f11.y, acc1.w);
        }
        if (j < m) {
            int s0 = ssrc[wid][j];
            float a0 = sp[wid][j][head];
            uint2 r0 = hp[s0 * (F1 / 4) + lane];
            float2 f00 = __half22float2(*reinterpret_cast<__half2*>(&r0.x));
            float2 f01 = __half22float2(*reinterpret_cast<__half2*>(&r0.y));
            acc0.x = fmaf(a0, f00.x, acc0.x); acc0.y = fmaf(a0, f00.y, acc0.y);
            acc0.z = fmaf(a0, f01.x, acc0.z); acc0.w = fmaf(a0, f01.y, acc0.w);
        }
        __syncwarp();
    }

    float4 acc;
    acc.x = acc0.x + acc1.x;
    acc.y = acc0.y + acc1.y;
    acc.z = acc0.z + acc1.z;
    acc.w = acc0.w + acc1.w;

#pragma unroll
    for (int o = 16; o > 0; o >>= 1) {
        sumv.x += __shfl_xor_sync(0xffffffffu, sumv.x, o);
        sumv.y += __shfl_xor_sync(0xffffffffu, sumv.y, o);
        sumv.z += __shfl_xor_sync(0xffffffffu, sumv.z, o);
        sumv.w += __shfl_xor_sync(0xffffffffu, sumv.w, o);
    }
    float sump = head == 0 ? sumv.x : head == 1 ? sumv.y : head == 2 ? sumv.z : sumv.w;
    float inv = 1.f / (sump + 1e-16f);
    float4 bb = *reinterpret_cast<const float4*>(&b1[lane * 4]);
    float4 o;
    o.x = acc.x * inv + bb.x; o.x = o.x > 0.f ? o.x : expm1f(o.x);
    o.y = acc.y * inv + bb.y; o.y = o.y > 0.f ? o.y : expm1f(o.y);
    o.z = acc.z * inv + bb.z; o.z = o.z > 0.f ? o.z : expm1f(o.z);
    o.w = acc.w * inv + bb.w; o.w = o.w > 0.f ? o.w : expm1f(o.w);
    // fp16 out1 write (uint2 = 4 halves, coalesced)
    __half2 h0 = __float22half2_rn(make_float2(o.x, o.y));
    __half2 h1 = __float22half2_rn(make_float2(o.z, o.w));
    uint2 pk;
    pk.x = *reinterpret_cast<unsigned int*>(&h0);
    pk.y = *reinterpret_cast<unsigned int*>(&h1);
    *reinterpret_cast<uint2*>(&g_out1h[n * F1 + lane * 4]) = pk;
}

// ---------------- layer-2 aggregation: one warp per dst node (R7 structure) ----------------
__global__ void __launch_bounds__(256, 8) agg2(float* __restrict__ out, const float* __restrict__ b2) {
    __shared__ float sp[8][32];
    __shared__ int ssrc[8][32];
    const int wid  = threadIdx.x >> 5;
    const int lane = threadIdx.x & 31;
    const int n    = (blockIdx.x * blockDim.x + threadIdx.x) >> 5;
    if (n >= NN) return;
    const int beg = g_rowptr[n], end = g_rowptr[n + 1];
    const float ad = g_ad2[n];
    const unsigned int* hp = reinterpret_cast<const unsigned int*>(g_h2h); // 2 halves/uint

    float sump = 0.f;
    float2 acc0 = make_float2(0.f, 0.f);
    float2 acc1 = make_float2(0.f, 0.f);

    for (int e0 = beg; e0 < end; e0 += 32) {
        const int m = min(32, end - e0);
        float p = 0.f;
        int s = 0;
        if (lane < m) {
            s = g_csrc[e0 + lane];
            p = lrexp(g_as2[s] + ad);
        }
        sump += p;
        sp[wid][lane] = p;
        ssrc[wid][lane] = s;
        __syncwarp();
        int j = 0;
        for (; j + 2 <= m; j += 2) {
            int s0 = ssrc[wid][j + 0];
            int s1 = ssrc[wid][j + 1];
            float a0 = sp[wid][j + 0];
            float a1 = sp[wid][j + 1];
            unsigned int r0 = hp[s0 * (F2 / 2) + lane];
            unsigned int r1 = hp[s1 * (F2 / 2) + lane];
            float2 f0 = __half22float2(*reinterpret_cast<__half2*>(&r0));
            float2 f1 = __half22float2(*reinterpret_cast<__half2*>(&r1));
            acc0.x = fmaf(a0, f0.x, acc0.x); acc0.y = fmaf(a0, f0.y, acc0.y);
            acc1.x = fmaf(a1, f1.x, acc1.x); acc1.y = fmaf(a1, f1.y, acc1.y);
        }
        if (j < m) {
            int s0 = ssrc[wid][j];
            float a0 = sp[wid][j];
            unsigned int r0 = hp[s0 * (F2 / 2) + lane];
            float2 f0 = __half22float2(*reinterpret_cast<__half2*>(&r0));
            acc0.x = fmaf(a0, f0.x, acc0.x); acc0.y = fmaf(a0, f0.y, acc0.y);
        }
        __syncwarp();
    }

    float2 acc;
    acc.x = acc0.x + acc1.x;
    acc.y = acc0.y + acc1.y;
#pragma unroll
    for (int o = 16; o > 0; o >>= 1)
        sump += __shfl_xor_sync(0xffffffffu, sump, o);
    float inv = 1.f / (sump + 1e-16f);
    float2 o;
    o.x = acc.x * inv + b2[lane * 2];
    o.y = acc.y * inv + b2[lane * 2 + 1];
    *reinterpret_cast<float2*>(&out[n * F2 + lane * 2]) = o;
}

// ---------------- launch ----------------
extern "C" void kernel_launch(void* const* d_in, const int* in_sizes, int n_in,
                              void* d_out, int out_size) {
    const float* x        = (const float*)d_in[0];
    const int*   ei_raw   = (const int*)d_in[1];
    const float* W1       = (const float*)d_in[2];
    const float* att_src1 = (const float*)d_in[3];
    const float* att_dst1 = (const float*)d_in[4];
    const float* b1       = (const float*)d_in[5];
    const float* W2       = (const float*)d_in[6];
    const float* att_src2 = (const float*)d_in[7];
    const float* att_dst2 = (const float*)d_in[8];
    const float* b2       = (const float*)d_in[9];
    float* out = (float*)d_out;

    static cudaStream_t sCsr = nullptr;
    static cudaEvent_t evFork = nullptr, evJoin = nullptr;
    if (sCsr == nullptr) {
        cudaStreamCreateWithFlags(&sCsr, cudaStreamNonBlocking);
        cudaEventCreateWithFlags(&evFork, cudaEventDisableTiming);
        cudaEventCreateWithFlags(&evJoin, cudaEventDisableTiming);
    }

    cudaEventRecord(evFork, 0);
    cudaStreamWaitEvent(sCsr, evFork, 0);

    // layer 1 GEMM + att epilogue (default stream)
    sgemm<128, 128, 16, 8, 8, 1><<<(NN + 127) / 128, 256>>>(x, W1, att_src1, att_dst1, NN);

    // CSR build chain on sCsr, concurrent with layer-1 GEMM
    zero_cnt<<<(NN + 255) / 256, 256, 0, sCsr>>>();
    hist_edges<<<(NE + 255) / 256, 256, 0, sCsr>>>(ei_raw);
    scanA<<<NBLK, SCAN_B, 0, sCsr>>>();
    scanB<<<1, 64, 0, sCsr>>>();
    scanC<<<NBLK, SCAN_B, 0, sCsr>>>();
    scatter_edges<<<(NE + 255) / 256, 256, 0, sCsr>>>(ei_raw);
    cudaEventRecord(evJoin, sCsr);

    // ---- join, then aggregation ----
    cudaStreamWaitEvent(0, evJoin, 0);
    agg1<<<(NN * 32 + 255) / 256, 256>>>(b1);

    // ---- layer 2 ----
    sgemm<128, 64, 16, 8, 4, 2><<<(NN + 127) / 128, 256>>>(nullptr, W2, att_src2, att_dst2, NN);
    agg2<<<(NN * 32 + 255) / 256, 256>>>(out, b2);
}

// round 15
// speedup vs baseline: 1.0893x; 1.0893x over previous
#include <cuda_runtime.h>
#include <cuda_fp16.h>

// ---------------- problem constants ----------------
#define NN 50000      // nodes
#define NE 800000     // edges
#define IC 128        // input channels
#define F1 128        // layer1 out = heads*hid = 4*32
#define H  4          // layer1 heads
#define F2 64         // layer2 out channels
#define SCAN_B 1024
#define NBLK ((NN + SCAN_B - 1) / SCAN_B)   // 49

// ---------------- device scratch ----------------
__device__ __half g_h1h[NN * F1];   // layer1 node features, fp16 (gather payload)
__device__ float g_as1[NN * H];
__device__ float g_ad1[NN * H];
__device__ __half g_out1h[NN * F1]; // layer1 output (norm+bias+elu), fp16
__device__ __half g_h2h[NN * F2];   // layer2 node features, fp16
__device__ float g_as2[NN];
__device__ float g_ad2[NN];
__device__ int   g_cnt[NN];         // degree histogram / scatter counters
__device__ int   g_rowptr[NN + 1];
__device__ int   g_csrc[NE];        // src ids sorted by dst (CSR)
__device__ int   g_bsum[NBLK];
__device__ int   g_boff[NBLK];

// ---------------- helpers ----------------
__device__ __forceinline__ float lrexp(float t) {
    t = t > 0.f ? t : 0.2f * t;      // LeakyReLU(0.2)
    return __expf(t);
}

__device__ __forceinline__ int detect_is64(const int* __restrict__ raw) {
    int nz = 0;
#pragma unroll
    for (int k = 0; k < 64; k++) nz |= raw[2 * (k * 631) + 1];
    return (nz == 0) ? 1 : 0;
}

// ---------------- CSR build ----------------
__global__ void zero_cnt() {
    int i = blockIdx.x * blockDim.x + threadIdx.x;
    if (i < NN) g_cnt[i] = 0;
}

__global__ void hist_edges(const int* __restrict__ raw) {
    __shared__ int s_is64;
    if (threadIdx.x == 0) s_is64 = detect_is64(raw);
    __syncthreads();
    int i = blockIdx.x * blockDim.x + threadIdx.x;
    if (i >= NE) return;
    int d = s_is64 ? reinterpret_cast<const int2*>(raw)[NE + i].x : raw[NE + i];
    atomicAdd(&g_cnt[d], 1);
}

__global__ void scanA() {
    __shared__ int s[32];
    int idx = blockIdx.x * SCAN_B + threadIdx.x;
    int v = (idx < NN) ? g_cnt[idx] : 0;
#pragma unroll
    for (int o = 16; o > 0; o >>= 1) v += __shfl_down_sync(0xffffffffu, v, o);
    if ((threadIdx.x & 31) == 0) s[threadIdx.x >> 5] = v;
    __syncthreads();
    if (threadIdx.x < 32) {
        int u = s[threadIdx.x];
#pragma unroll
        for (int o = 16; o > 0; o >>= 1) u += __shfl_down_sync(0xffffffffu, u, o);
        if (threadIdx.x == 0) g_bsum[blockIdx.x] = u;
    }
}

__global__ void scanB() {
    __shared__ int s[64];
    int t = threadIdx.x;
    int v = (t < NBLK) ? g_bsum[t] : 0;
    s[t] = v;
    __syncthreads();
#pragma unroll
    for (int off = 1; off < 64; off <<= 1) {
        int u = (t >= off) ? s[t - off] : 0;
        __syncthreads();
        s[t] += u;
        __syncthreads();
    }
    if (t < NBLK) g_boff[t] = s[t] - v;   // exclusive
}

__global__ void scanC() {
    __shared__ int s[SCAN_B];
    int t = threadIdx.x;
    int idx = blockIdx.x * SCAN_B + t;
    int v = (idx < NN) ? g_cnt[idx] : 0;
    s[t] = v;
    __syncthreads();
    for (int off = 1; off < SCAN_B; off <<= 1) {
        int u = (t >= off) ? s[t - off] : 0;
        __syncthreads();
        s[t] += u;
        __syncthreads();
    }
    int excl = s[t] - v + g_boff[blockIdx.x];
    if (idx < NN) {
        g_rowptr[idx] = excl;
        g_cnt[idx] = 0;
    }
    if (idx == NN - 1) g_rowptr[NN] = excl + v;
}

__global__ void scatter_edges(const int* __restrict__ raw) {
    __shared__ int s_is64;
    if (threadIdx.x == 0) s_is64 = detect_is64(raw);
    __syncthreads();
    int i = blockIdx.x * blockDim.x + threadIdx.x;
    if (i >= NE) return;
    int s, d;
    if (s_is64) {
        s = reinterpret_cast<const int2*>(raw)[i].x;
        d = reinterpret_cast<const int2*>(raw)[NE + i].x;
    } else {
        s = raw[i];
        d = raw[NE + i];
    }
    int pos = g_rowptr[d] + atomicAdd(&g_cnt[d], 1);
    g_csrc[pos] = s;
}

// ---------------- SGEMM + fused attention-coefficient epilogue ----------------
// LAYER=1: A = x (fp32), C = g_h1h fp16; epilogue -> g_as1/g_ad1
// LAYER=2: A = g_out1h (fp16, converted on load), C = g_h2h; epilogue -> g_as2/g_ad2
template <int BM, int BN, int BK, int TM, int TN, int LAYER>
__global__ void __launch_bounds__((BM / TM) * (BN / TN), 2)
sgemm(const float* __restrict__ Ain, const float* __restrict__ B,
      const float* __restrict__ attS, const float* __restrict__ attD, int M) {
    constexpr int K = 128;
    constexpr int NT = (BM / TM) * (BN / TN);
    constexpr int A_IT = BM * BK / (4 * NT);
    constexpr int B_IT = BK * BN / (4 * NT);
    __half* C = (LAYER == 1) ? g_h1h : g_h2h;

    __shared__ __align__(16) float As[2][BK][BM];   // transposed: As[k][m]
    __shared__ __align__(16) float Bs[2][BK][BN];

    const int tid  = threadIdx.x;
    const int trow = tid / (BN / TN);
    const int tcol = tid % (BN / TN);
    const int rowBase = blockIdx.x * BM;

    float4 aReg[A_IT], bReg[B_IT];

    auto gload = [&](int k0) {
#pragma unroll
        for (int it = 0; it < A_IT; it++) {
            int i = (tid + it * NT) * 4;
            int r = i / BK, c = i % BK;
            int gr = rowBase + r;
            float4 v = make_float4(0.f, 0.f, 0.f, 0.f);
            if (gr < M) {
                if (LAYER == 1) {
                    v = *reinterpret_cast<const float4*>(&Ain[(long)gr * K + k0 + c]);
                } else {
                    uint2 hv = *reinterpret_cast<const uint2*>(&g_out1h[(long)gr * K + k0 + c]);
                    float2 lo = __half22float2(*reinterpret_cast<__half2*>(&hv.x));
                    float2 hi = __half22float2(*reinterpret_cast<__half2*>(&hv.y));
                    v = make_float4(lo.x, lo.y, hi.x, hi.y);
                }
            }
            aReg[it] = v;
        }
#pragma unroll
        for (int it = 0; it < B_IT; it++) {
            int i = (tid + it * NT) * 4;
            int r = i / BN, c = i % BN;
            bReg[it] = *reinterpret_cast<const float4*>(&B[(long)(k0 + r) * BN + c]);
        }
    };

    auto sstore = [&](int buf) {
#pragma unroll
        for (int it = 0; it < A_IT; it++) {
            int i = (tid + it * NT) * 4;
            int r = i / BK, c = i % BK;
            As[buf][c + 0][r] = aReg[it].x;
            As[buf][c + 1][r] = aReg[it].y;
            As[buf][c + 2][r] = aReg[it].z;
            As[buf][c + 3][r] = aReg[it].w;
        }
#pragma unroll
        for (int it = 0; it < B_IT; it++) {
            int i = (tid + it * NT) * 4;
            int r = i / BN, c = i % BN;
            *reinterpret_cast<float4*>(&Bs[buf][r][c]) = bReg[it];
        }
    };

    float acc[TM][TN];
#pragma unroll
    for (int m = 0; m < TM; m++)
#pragma unroll
        for (int n = 0; n < TN; n++) acc[m][n] = 0.f;

    auto compute = [&](int buf) {
#pragma unroll
        for (int k = 0; k < BK; k++) {
            float ra[TM], rb[TN];
#pragma unroll
            for (int m = 0; m < TM; m += 4)
                *reinterpret_cast<float4*>(&ra[m]) =
                    *reinterpret_cast<const float4*>(&As[buf][k][trow * TM + m]);
#pragma unroll
            for (int n = 0; n < TN; n += 4)
                *reinterpret_cast<float4*>(&rb[n]) =
                    *reinterpret_cast<const float4*>(&Bs[buf][k][tcol * TN + n]);
#pragma unroll
            for (int m = 0; m < TM; m++)
#pragma unroll
                for (int n = 0; n < TN; n++)
                    acc[m][n] = fmaf(ra[m], rb[n], acc[m][n]);
        }
    };

    gload(0);
    sstore(0);
    __syncthreads();
    int buf = 0;
    for (int k0 = BK; k0 < K; k0 += BK) {
        gload(k0);
        compute(buf);
        sstore(buf ^ 1);
        __syncthreads();
        buf ^= 1;
    }
    compute(buf);

    // ---- write C tile in fp16 ----
#pragma unroll
    for (int m = 0; m < TM; m++) {
        int gr = rowBase + trow * TM + m;
        if (gr < M) {
            unsigned int packed[TN / 2];
#pragma unroll
            for (int n = 0; n < TN; n += 2) {
                __half2 h = __float22half2_rn(make_float2(acc[m][n], acc[m][n + 1]));
                packed[n / 2] = *reinterpret_cast<unsigned int*>(&h);
            }
            __half* dst = &C[(long)gr * BN + tcol * TN];
            if (TN == 8) {
                *reinterpret_cast<uint4*>(dst) =
                    make_uint4(packed[0], packed[1], packed[2], packed[3]);
            } else {
                *reinterpret_cast<uint2*>(dst) = make_uint2(packed[0], packed[1]);
            }
        }
    }

    // ---- fused attention epilogue (fp32 acc) ----
    float asr[TN], adr[TN];
#pragma unroll
    for (int n = 0; n < TN; n++) {
        asr[n] = attS[tcol * TN + n];
        adr[n] = attD[tcol * TN + n];
    }
    float pa[TM], pd[TM];
#pragma unroll
    for (int m = 0; m < TM; m++) {
        float a = 0.f, b = 0.f;
#pragma unroll
        for (int n = 0; n < TN; n++) {
            a = fmaf(acc[m][n], asr[n], a);
            b = fmaf(acc[m][n], adr[n], b);
        }
        if (LAYER == 1) {
            a += __shfl_down_sync(0xffffffffu, a, 2);
            a += __shfl_down_sync(0xffffffffu, a, 1);
            b += __shfl_down_sync(0xffffffffu, b, 2);
            b += __shfl_down_sync(0xffffffffu, b, 1);
        } else {
            a += __shfl_down_sync(0xffffffffu, a, 8);
            a += __shfl_down_sync(0xffffffffu, a, 4);
            a += __shfl_down_sync(0xffffffffu, a, 2);
            a += __shfl_down_sync(0xffffffffu, a, 1);
            b += __shfl_down_sync(0xffffffffu, b, 8);
            b += __shfl_down_sync(0xffffffffu, b, 4);
            b += __shfl_down_sync(0xffffffffu, b, 2);
            b += __shfl_down_sync(0xffffffffu, b, 1);
        }
        pa[m] = a;
        pd[m] = b;
    }

    float* sA = &Bs[0][0][0];
    float* sD = sA + BM * H;
    __syncthreads();

    if (LAYER == 1) {
        if ((tcol & 3) == 0) {
            int head = tcol >> 2;
#pragma unroll
            for (int m = 0; m < TM; m++) {
                sA[(trow * TM + m) * H + head] = pa[m];
                sD[(trow * TM + m) * H + head] = pd[m];
            }
        }
        __syncthreads();
        if (tid < BM) {
            int gr = rowBase + tid;
            if (gr < M) {
                *reinterpret_cast<float4*>(&g_as1[gr * H]) =
                    *reinterpret_cast<const float4*>(&sA[tid * H]);
                *reinterpret_cast<float4*>(&g_ad1[gr * H]) =
                    *reinterpret_cast<const float4*>(&sD[tid * H]);
            }
        }
    } else {
        if (tcol == 0) {
#pragma unroll
            for (int m = 0; m < TM; m++) {
                sA[trow * TM + m] = pa[m];
                sD[trow * TM + m] = pd[m];
            }
        }
        __syncthreads();
        if (tid < BM) {
            int gr = rowBase + tid;
            if (gr < M) {
                g_as2[gr] = sA[tid];
                g_ad2[gr] = sD[tid];
            }
        }
    }
}

// ---------------- layer-1 aggregation: one warp per dst node (R7 structure) ----------------
__global__ void __launch_bounds__(256) agg1(const float* __restrict__ b1) {
    __shared__ __align__(16) float sp[8][32][4];   // staged p per head
    __shared__ int ssrc[8][32];
    const int wid  = threadIdx.x >> 5;
    const int lane = threadIdx.x & 31;
    const int n    = (blockIdx.x * blockDim.x + threadIdx.x) >> 5;
    if (n >= NN) return;
    const int beg = g_rowptr[n], end = g_rowptr[n + 1];
    const int head = lane >> 3;
    const float4 ad = *reinterpret_cast<const float4*>(&g_ad1[n * H]);
    const uint2* hp = reinterpret_cast<const uint2*>(g_h1h);   // 4 halves per uint2

    float4 sumv = make_float4(0.f, 0.f, 0.f, 0.f);
    float4 acc0 = make_float4(0.f, 0.f, 0.f, 0.f);
    float4 acc1 = make_float4(0.f, 0.f, 0.f, 0.f);

    for (int e0 = beg; e0 < end; e0 += 32) {
        const int m = min(32, end - e0);
        float4 p4 = make_float4(0.f, 0.f, 0.f, 0.f);
        int s = 0;
        if (lane < m) {
            s = g_csrc[e0 + lane];
            float4 as = *reinterpret_cast<const float4*>(&g_as1[s * H]);
            p4.x = lrexp(as.x + ad.x);
            p4.y = lrexp(as.y + ad.y);
            p4.z = lrexp(as.z + ad.z);
            p4.w = lrexp(as.w + ad.w);
        }
        sumv.x += p4.x; sumv.y += p4.y; sumv.z += p4.z; sumv.w += p4.w;
        *reinterpret_cast<float4*>(&sp[wid][lane][0]) = p4;
        ssrc[wid][lane] = s;
        __syncwarp();
        int j = 0;
        for (; j + 2 <= m; j += 2) {
            int s0 = ssrc[wid][j + 0];
            int s1 = ssrc[wid][j + 1];
            float a0 = sp[wid][j + 0][head];
            float a1 = sp[wid][j + 1][head];
            uint2 r0 = hp[s0 * (F1 / 4) + lane];
            uint2 r1 = hp[s1 * (F1 / 4) + lane];
            float2 f00 = __half22float2(*reinterpret_cast<__half2*>(&r0.x));
            float2 f01 = __half22float2(*reinterpret_cast<__half2*>(&r0.y));
            float2 f10 = __half22float2(*reinterpret_cast<__half2*>(&r1.x));
            float2 f11 = __half22float2(*reinterpret_cast<__half2*>(&r1.y));
            acc0.x = fmaf(a0, f00.x, acc0.x); acc0.y = fmaf(a0, f00.y, acc0.y);
            acc0.z = fmaf(a0, f01.x, acc0.z); acc0.w = fmaf(a0, f01.y, acc0.w);
            acc1.x = fmaf(a1, f10.x, acc1.x); acc1.y = fmaf(a1, f10.y, acc1.y);
            acc1.z = fmaf(a1, f11.x, acc1.z); acc1.w = fmaf(a1, f11.y, acc1.w);
        }
        if (j < m) {
            int s0 = ssrc[wid][j];
            float a0 = sp[wid][j][head];
            uint2 r0 = hp[s0 * (F1 / 4) + lane];
            float2 f00 = __half22float2(*reinterpret_cast<__half2*>(&r0.x));
            float2 f01 = __half22float2(*reinterpret_cast<__half2*>(&r0.y));
            acc0.x = fmaf(a0, f00.x, acc0.x); acc0.y = fmaf(a0, f00.y, acc0.y);
            acc0.z = fmaf(a0, f01.x, acc0.z); acc0.w = fmaf(a0, f01.y, acc0.w);
        }
        __syncwarp();
    }

    float4 acc;
    acc.x = acc0.x + acc1.x;
    acc.y = acc0.y + acc1.y;
    acc.z = acc0.z + acc1.z;
    acc.w = acc0.w + acc1.w;

#pragma unroll
    for (int o = 16; o > 0; o >>= 1) {
        sumv.x += __shfl_xor_sync(0xffffffffu, sumv.x, o);
        sumv.y += __shfl_xor_sync(0xffffffffu, sumv.y, o);
        sumv.z += __shfl_xor_sync(0xffffffffu, sumv.z, o);
        sumv.w += __shfl_xor_sync(0xffffffffu, sumv.w, o);
    }
    float sump = head == 0 ? sumv.x : head == 1 ? sumv.y : head == 2 ? sumv.z : sumv.w;
    float inv = 1.f / (sump + 1e-16f);
    float4 bb = *reinterpret_cast<const float4*>(&b1[lane * 4]);
    float4 o;
    o.x = acc.x * inv + bb.x; o.x = o.x > 0.f ? o.x : expm1f(o.x);
    o.y = acc.y * inv + bb.y; o.y = o.y > 0.f ? o.y : expm1f(o.y);
    o.z = acc.z * inv + bb.z; o.z = o.z > 0.f ? o.z : expm1f(o.z);
    o.w = acc.w * inv + bb.w; o.w = o.w > 0.f ? o.w : expm1f(o.w);
    // fp16 out1 write (uint2 = 4 halves, coalesced)
    __half2 h0 = __float22half2_rn(make_float2(o.x, o.y));
    __half2 h1 = __float22half2_rn(make_float2(o.z, o.w));
    uint2 pk;
    pk.x = *reinterpret_cast<unsigned int*>(&h0);
    pk.y = *reinterpret_cast<unsigned int*>(&h1);
    *reinterpret_cast<uint2*>(&g_out1h[n * F1 + lane * 4]) = pk;
}

// ---------------- layer-2 aggregation: one warp per dst node (R7 structure) ----------------
__global__ void __launch_bounds__(256) agg2(float* __restrict__ out, const float* __restrict__ b2) {
    __shared__ float sp[8][32];
    __shared__ int ssrc[8][32];
    const int wid  = threadIdx.x >> 5;
    const int lane = threadIdx.x & 31;
    const int n    = (blockIdx.x * blockDim.x + threadIdx.x) >> 5;
    if (n >= NN) return;
    const int beg = g_rowptr[n], end = g_rowptr[n + 1];
    const float ad = g_ad2[n];
    const unsigned int* hp = reinterpret_cast<const unsigned int*>(g_h2h); // 2 halves/uint

    float sump = 0.f;
    float2 acc0 = make_float2(0.f, 0.f);
    float2 acc1 = make_float2(0.f, 0.f);

    for (int e0 = beg; e0 < end; e0 += 32) {
        const int m = min(32, end - e0);
        float p = 0.f;
        int s = 0;
        if (lane < m) {
            s = g_csrc[e0 + lane];
            p = lrexp(g_as2[s] + ad);
        }
        sump += p;
        sp[wid][lane] = p;
        ssrc[wid][lane] = s;
        __syncwarp();
        int j = 0;
        for (; j + 2 <= m; j += 2) {
            int s0 = ssrc[wid][j + 0];
            int s1 = ssrc[wid][j + 1];
            float a0 = sp[wid][j + 0];
            float a1 = sp[wid][j + 1];
            unsigned int r0 = hp[s0 * (F2 / 2) + lane];
            unsigned int r1 = hp[s1 * (F2 / 2) + lane];
            float2 f0 = __half22float2(*reinterpret_cast<__half2*>(&r0));
            float2 f1 = __half22float2(*reinterpret_cast<__half2*>(&r1));
            acc0.x = fmaf(a0, f0.x, acc0.x); acc0.y = fmaf(a0, f0.y, acc0.y);
            acc1.x = fmaf(a1, f1.x, acc1.x); acc1.y = fmaf(a1, f1.y, acc1.y);
        }
        if (j < m) {
            int s0 = ssrc[wid][j];
            float a0 = sp[wid][j];
            unsigned int r0 = hp[s0 * (F2 / 2) + lane];
            float2 f0 = __half22float2(*reinterpret_cast<__half2*>(&r0));
            acc0.x = fmaf(a0, f0.x, acc0.x); acc0.y = fmaf(a0, f0.y, acc0.y);
        }
        __syncwarp();
    }

    float2 acc;
    acc.x = acc0.x + acc1.x;
    acc.y = acc0.y + acc1.y;
#pragma unroll
    for (int o = 16; o > 0; o >>= 1)
        sump += __shfl_xor_sync(0xffffffffu, sump, o);
    float inv = 1.f / (sump + 1e-16f);
    float2 o;
    o.x = acc.x * inv + b2[lane * 2];
    o.y = acc.y * inv + b2[lane * 2 + 1];
    *reinterpret_cast<float2*>(&out[n * F2 + lane * 2]) = o;
}

// ---------------- launch ----------------
extern "C" void kernel_launch(void* const* d_in, const int* in_sizes, int n_in,
                              void* d_out, int out_size) {
    const float* x        = (const float*)d_in[0];
    const int*   ei_raw   = (const int*)d_in[1];
    const float* W1       = (const float*)d_in[2];
    const float* att_src1 = (const float*)d_in[3];
    const float* att_dst1 = (const float*)d_in[4];
    const float* b1       = (const float*)d_in[5];
    const float* W2       = (const float*)d_in[6];
    const float* att_src2 = (const float*)d_in[7];
    const float* att_dst2 = (const float*)d_in[8];
    const float* b2       = (const float*)d_in[9];
    float* out = (float*)d_out;

    static cudaStream_t sCsr = nullptr;
    static cudaEvent_t evFork = nullptr, evJoin = nullptr;
    if (sCsr == nullptr) {
        cudaStreamCreateWithFlags(&sCsr, cudaStreamNonBlocking);
        cudaEventCreateWithFlags(&evFork, cudaEventDisableTiming);
        cudaEventCreateWithFlags(&evJoin, cudaEventDisableTiming);
    }

    cudaEventRecord(evFork, 0);
    cudaStreamWaitEvent(sCsr, evFork, 0);

    // layer 1 GEMM + att epilogue (default stream)
    sgemm<128, 128, 16, 8, 8, 1><<<(NN + 127) / 128, 256>>>(x, W1, att_src1, att_dst1, NN);

    // CSR build chain on sCsr, concurrent with layer-1 GEMM
    zero_cnt<<<(NN + 255) / 256, 256, 0, sCsr>>>();
    hist_edges<<<(NE + 255) / 256, 256, 0, sCsr>>>(ei_raw);
    scanA<<<NBLK, SCAN_B, 0, sCsr>>>();
    scanB<<<1, 64, 0, sCsr>>>();
    scanC<<<NBLK, SCAN_B, 0, sCsr>>>();
    scatter_edges<<<(NE + 255) / 256, 256, 0, sCsr>>>(ei_raw);
    cudaEventRecord(evJoin, sCsr);

    // ---- join, then aggregation ----
    cudaStreamWaitEvent(0, evJoin, 0);
    agg1<<<(NN * 32 + 255) / 256, 256>>>(b1);

    // ---- layer 2 ----
    sgemm<128, 64, 16, 8, 4, 2><<<(NN + 127) / 128, 256>>>(nullptr, W2, att_src2, att_dst2, NN);
    agg2<<<(NN * 32 + 255) / 256, 256>>>(out, b2);
}